// round 10
// baseline (speedup 1.0000x reference)
#include <cuda_runtime.h>
#include <cuda_fp16.h>

#define NN   100000
#define FIN  256
#define HDIM 128
#define CDIM 64
#define MAXE 1600000
#define NCSR 148                  // scan-pipeline blocks (co-resident wave 1)
#define GB1  ((NN + 127) / 128)   // gemm1 tiles = 782
#define CB   391                  // histogram blocks in mega
#define ZB   128                  // tail-zero blocks in mega
#define ZD   ((NN + 255) / 256)   // deg-zero blocks appended to score

// Scratch (static device globals — allocation-free per harness rules)
__device__ int     g_degi[NN];              // zeroed at END of each call (k_score)
__device__ int     g_rowptr[NN + 1];
__device__ int     g_bsum[NCSR];
__device__ int     g_boff[NCSR];
__device__ int     g_cursor[NN];
__device__ int     g_esrc[MAXE];            // edge sources grouped by dst (CSR)
__device__ float   g_dis[NN];
__device__ __half2 g_hw1h[NN * HDIM / 2];   // fp16: (x@W1)[v]  (UNSCALED)
__device__ float   g_agg1[NN * HDIM];       // fp32: relu(layer-1 aggregate)
__device__ __half2 g_hw2h[NN * CDIM / 2];   // fp16: dis[v]*(agg1@W2)[v]
__device__ __half2 g_agg2h[NN * CDIM / 2];  // fp16: final h2
__device__ int     g_barc;                  // barrier arrive counter
__device__ int     g_barg;                  // barrier generation

__device__ __forceinline__ void cp_async16(void* smem, const void* gmem) {
    unsigned s = (unsigned)__cvta_generic_to_shared(smem);
    asm volatile("cp.async.ca.shared.global [%0], [%1], 16;\n" :: "r"(s), "l"(gmem));
}
__device__ __forceinline__ void cp_commit() { asm volatile("cp.async.commit_group;\n"); }
__device__ __forceinline__ void cp_wait0()  { asm volatile("cp.async.wait_group 0;\n" ::: "memory"); }

__device__ __forceinline__ unsigned f2tf32(float f) {
    unsigned u;
    asm("cvt.rna.tf32.f32 %0, %1;\n" : "=r"(u) : "f"(f));
    return u;
}

__device__ __forceinline__ void mma_tf32(float* d, const unsigned* a, const unsigned* b) {
    asm volatile(
        "mma.sync.aligned.m16n8k8.row.col.f32.tf32.tf32.f32 "
        "{%0,%1,%2,%3}, {%4,%5,%6,%7}, {%8,%9}, {%0,%1,%2,%3};\n"
        : "+f"(d[0]), "+f"(d[1]), "+f"(d[2]), "+f"(d[3])
        : "r"(a[0]), "r"(a[1]), "r"(a[2]), "r"(a[3]), "r"(b[0]), "r"(b[1]));
}

__device__ __forceinline__ void u4_to_f8(uint4 u, float* f) {
    float2 t;
    t = __half22float2(*(__half2*)&u.x); f[0] = t.x; f[1] = t.y;
    t = __half22float2(*(__half2*)&u.y); f[2] = t.x; f[3] = t.y;
    t = __half22float2(*(__half2*)&u.z); f[4] = t.x; f[5] = t.y;
    t = __half22float2(*(__half2*)&u.w); f[6] = t.x; f[7] = t.y;
}

// Grid barrier among NCSR co-resident blocks.
__device__ __forceinline__ void csr_barrier() {
    __syncthreads();
    if (threadIdx.x == 0) {
        int gen = atomicAdd(&g_barg, 0);
        __threadfence();
        int t = atomicAdd(&g_barc, 1);
        if (t == NCSR - 1) {
            atomicExch(&g_barc, 0);
            __threadfence();
            atomicAdd(&g_barg, 1);
        } else {
            while (atomicAdd(&g_barg, 0) == gen) { __nanosleep(64); }
        }
    }
    __syncthreads();
}

// ───────────────────────── TF32 tensor-core GEMM body ─────────────────────────
// SCALE_DIS ? C = fp16(dis[row]*(A@B)) : C = fp16(A@B).
// NOTE: g_* pointers must be resolved in DEVICE code (host shadow-symbol trap).
template<int BM, int BN, int BK, int WM, int WN, int NT, bool SCALE_DIS>
__device__ __forceinline__ void mma_body(
    int bx, const float* __restrict__ A, const float* __restrict__ Bg,
    __half2* __restrict__ C, int M, int N, int K)
{
    constexpr int BKp = BK + 4;
    constexpr int BNp = BN + 8;
    __shared__ float As[2][BM][BKp];
    __shared__ float Bs[2][BK][BNp];

    const int tid  = threadIdx.x;
    const int wid  = tid >> 5;
    const int lane = tid & 31;
    const int grp  = lane >> 2;
    const int qi   = lane & 3;
    constexpr int NWN = BN / WN;
    const int warp_m = wid / NWN;
    const int warp_n = wid % NWN;
    constexpr int MF = WM / 16;
    constexpr int NF = WN / 8;

    const int brow = bx * BM;

    float acc[MF][NF][4];
    #pragma unroll
    for (int i = 0; i < MF; i++)
        #pragma unroll
        for (int j = 0; j < NF; j++)
            #pragma unroll
            for (int q = 0; q < 4; q++) acc[i][j][q] = 0.0f;

    constexpr int AIT = (BM * BK / 4) / NT;
    constexpr int BIT = (BK * BN / 4) / NT;

    auto cpA = [&](int buf, int k0) {
        #pragma unroll
        for (int it = 0; it < AIT; it++) {
            int idx  = tid + it * NT;
            int row  = idx / (BK / 4);
            int kc   = (idx % (BK / 4)) * 4;
            int grow = brow + row;
            if (grow > M - 1) grow = M - 1;
            cp_async16(&As[buf][row][kc], A + (long long)grow * K + k0 + kc);
        }
    };
    auto cpB = [&](int buf, int k0) {
        #pragma unroll
        for (int it = 0; it < BIT; it++) {
            int idx = tid + it * NT;
            int kk  = idx / (BN / 4);
            int nc  = (idx % (BN / 4)) * 4;
            cp_async16(&Bs[buf][kk][nc], Bg + (long long)(k0 + kk) * N + nc);
        }
    };
    auto compute = [&](int buf) {
        #pragma unroll
        for (int ks = 0; ks < BK / 8; ks++) {
            int kk = ks * 8;
            unsigned a[MF][4], b[NF][2];
            #pragma unroll
            for (int fm = 0; fm < MF; fm++) {
                const float* ap = &As[buf][warp_m * WM + fm * 16 + grp][kk + qi];
                a[fm][0] = f2tf32(ap[0]);
                a[fm][1] = f2tf32(ap[8 * BKp]);
                a[fm][2] = f2tf32(ap[4]);
                a[fm][3] = f2tf32(ap[8 * BKp + 4]);
            }
            #pragma unroll
            for (int fn = 0; fn < NF; fn++) {
                const float* bp = &Bs[buf][kk + qi][warp_n * WN + fn * 8 + grp];
                b[fn][0] = f2tf32(bp[0]);
                b[fn][1] = f2tf32(bp[4 * BNp]);
            }
            #pragma unroll
            for (int fm = 0; fm < MF; fm++)
                #pragma unroll
                for (int fn = 0; fn < NF; fn++)
                    mma_tf32(acc[fm][fn], a[fm], b[fn]);
        }
    };

    cpA(0, 0); cpB(0, 0); cp_commit();
    cp_wait0(); __syncthreads();

    const int KT = K / BK;
    for (int t = 1; t < KT; t++) {
        cpA(t & 1, t * BK); cpB(t & 1, t * BK); cp_commit();
        compute((t - 1) & 1);
        cp_wait0(); __syncthreads();
    }
    compute((KT - 1) & 1);

    #pragma unroll
    for (int fm = 0; fm < MF; fm++) {
        int r0 = brow + warp_m * WM + fm * 16 + grp;
        int r1 = r0 + 8;
        float d0 = 1.0f, d1 = 1.0f;
        if (SCALE_DIS) {
            d0 = (r0 < M) ? g_dis[r0] : 0.0f;
            d1 = (r1 < M) ? g_dis[r1] : 0.0f;
        }
        #pragma unroll
        for (int fn = 0; fn < NF; fn++) {
            int col = warp_n * WN + fn * 8 + 2 * qi;
            if (r0 < M)
                C[((long long)r0 * N + col) >> 1] =
                    __floats2half2_rn(acc[fm][fn][0] * d0, acc[fm][fn][1] * d0);
            if (r1 < M)
                C[((long long)r1 * N + col) >> 1] =
                    __floats2half2_rn(acc[fm][fn][2] * d1, acc[fm][fn][3] * d1);
        }
    }
}

// ───────────────────────── mega: gemm1 ∥ histogram ∥ tail-zero ─────────────────
// g_degi enters this kernel ZEROED (invariant maintained by k_score's tail).
__global__ void __launch_bounds__(256)
k_mega(const float* __restrict__ x, const float* __restrict__ W1,
       const int* __restrict__ dst, int E,
       float* __restrict__ out, int SE, int total)
{
    int bx = blockIdx.x;
    if (bx < GB1) {   // gemm1: hw1h = fp16(x @ W1), unscaled
        mma_body<128, 128, 16, 64, 32, 256, false>(bx, x, W1, g_hw1h, NN, HDIM, FIN);
        return;
    }
    bx -= GB1;
    if (bx < CB) {    // degree histogram
        for (int e = bx * 256 + threadIdx.x; e < E; e += CB * 256)
            atomicAdd(&g_degi[dst[e]], 1);
        return;
    }
    bx -= CB;         // zero the tail of the output
    for (int i = SE + bx * 256 + threadIdx.x; i < total; i += ZB * 256)
        out[i] = 0.0f;
}

// ───────────────────────── fused 3-phase scan (148 blocks, grid barriers) ──────
__global__ void __launch_bounds__(256)
k_scan(int E)
{
    const int c   = blockIdx.x;
    const int tid = threadIdx.x;
    __shared__ int sc[256];
    const int chunk = (NN + NCSR - 1) / NCSR;
    const int lo = c * chunk;
    const int hi = (lo + chunk < NN) ? lo + chunk : NN;

    // Phase A: per-block chunk sums.
    {
        int s = 0;
        for (int i = lo + tid; i < hi; i += 256) s += g_degi[i];
        sc[tid] = s; __syncthreads();
        #pragma unroll
        for (int o = 128; o; o >>= 1) {
            if (tid < o) sc[tid] += sc[tid + o];
            __syncthreads();
        }
        if (tid == 0) g_bsum[c] = sc[0];
    }
    csr_barrier();

    // Phase B: block 0 exclusive-scans the chunk sums.
    if (c == 0) {
        int v = (tid < NCSR) ? g_bsum[tid] : 0;
        sc[tid] = v; __syncthreads();
        #pragma unroll
        for (int o = 1; o < 256; o <<= 1) {
            int t2 = (tid >= o) ? sc[tid - o] : 0;
            __syncthreads();
            sc[tid] += t2;
            __syncthreads();
        }
        if (tid < NCSR) g_boff[tid] = sc[tid] - v;
    }
    csr_barrier();

    // Phase C: rowptr / cursor / dis over the chunk.
    {
        int running = g_boff[c];
        for (int base = lo; base < hi; base += 256) {
            int i = base + tid;
            int d = (i < hi) ? g_degi[i] : 0;
            sc[tid] = d; __syncthreads();
            #pragma unroll
            for (int o = 1; o < 256; o <<= 1) {
                int t2 = (tid >= o) ? sc[tid - o] : 0;
                __syncthreads();
                sc[tid] += t2;
                __syncthreads();
            }
            if (i < hi) {
                int r = running + sc[tid] - d;
                g_rowptr[i] = r;
                g_cursor[i] = r;
                g_dis[i]    = rsqrtf((float)d + 1.0f);
            }
            running += sc[255];
            __syncthreads();
        }
        if (c == 0 && tid == 0) g_rowptr[NN] = E;
    }
}

__global__ void k_bin(const int* __restrict__ src, const int* __restrict__ dst, int E) {
    int e = blockIdx.x * blockDim.x + threadIdx.x;
    if (e >= E) return;
    int d = dst[e];
    int p = atomicAdd(&g_cursor[d], 1);
    g_esrc[p] = src[e];
}

// ───────────────────────── gather aggregation (4-edge unroll) ──────────────────
// Layer 1: hw1h UNSCALED.  S = dv*h1[v] + Σ_e ds*h1[s];  agg1 = relu(dv*S + b1).
__global__ void k_gather1(const float* __restrict__ b1) {
    int t = blockIdx.x * blockDim.x + threadIdx.x;
    int v = t >> 4, lane = t & 15;
    if (v >= NN) return;
    int beg = g_rowptr[v], end = g_rowptr[v + 1];
    float dv = g_dis[v];
    const uint4* hw = (const uint4*)g_hw1h;   // 16 uint4 per row

    float a[8], a2[8], f[8];
    u4_to_f8(hw[(long long)v * 16 + lane], f);
    #pragma unroll
    for (int i = 0; i < 8; i++) { a[i] = dv * f[i]; a2[i] = 0.f; }

    int p = beg;
    for (; p + 3 < end; p += 4) {
        int s0 = __ldg(&g_esrc[p]);
        int s1 = __ldg(&g_esrc[p + 1]);
        int s2 = __ldg(&g_esrc[p + 2]);
        int s3 = __ldg(&g_esrc[p + 3]);
        float d0 = g_dis[s0], d1 = g_dis[s1], d2 = g_dis[s2], d3 = g_dis[s3];
        uint4 u0 = hw[(long long)s0 * 16 + lane];
        uint4 u1 = hw[(long long)s1 * 16 + lane];
        uint4 u2 = hw[(long long)s2 * 16 + lane];
        uint4 u3 = hw[(long long)s3 * 16 + lane];
        float f0[8], f1[8], f2[8], f3[8];
        u4_to_f8(u0, f0); u4_to_f8(u1, f1); u4_to_f8(u2, f2); u4_to_f8(u3, f3);
        #pragma unroll
        for (int i = 0; i < 8; i++) {
            a[i]  = fmaf(d0, f0[i], a[i]);
            a2[i] = fmaf(d1, f1[i], a2[i]);
            a[i]  = fmaf(d2, f2[i], a[i]);
            a2[i] = fmaf(d3, f3[i], a2[i]);
        }
    }
    for (; p < end; p++) {
        int s0 = __ldg(&g_esrc[p]);
        float d0 = g_dis[s0];
        float f0[8];
        u4_to_f8(hw[(long long)s0 * 16 + lane], f0);
        #pragma unroll
        for (int i = 0; i < 8; i++) a[i] = fmaf(d0, f0[i], a[i]);
    }
    float4 b0 = ((const float4*)b1)[lane * 2];
    float4 b1v = ((const float4*)b1)[lane * 2 + 1];
    float o[8];
    o[0] = fmaxf(fmaf(dv, a[0] + a2[0], b0.x), 0.f);
    o[1] = fmaxf(fmaf(dv, a[1] + a2[1], b0.y), 0.f);
    o[2] = fmaxf(fmaf(dv, a[2] + a2[2], b0.z), 0.f);
    o[3] = fmaxf(fmaf(dv, a[3] + a2[3], b0.w), 0.f);
    o[4] = fmaxf(fmaf(dv, a[4] + a2[4], b1v.x), 0.f);
    o[5] = fmaxf(fmaf(dv, a[5] + a2[5], b1v.y), 0.f);
    o[6] = fmaxf(fmaf(dv, a[6] + a2[6], b1v.z), 0.f);
    o[7] = fmaxf(fmaf(dv, a[7] + a2[7], b1v.w), 0.f);
    float4* outp = (float4*)(g_agg1 + (long long)v * HDIM + lane * 8);
    outp[0] = make_float4(o[0], o[1], o[2], o[3]);
    outp[1] = make_float4(o[4], o[5], o[6], o[7]);
}

// Layer 2: hw2h pre-scaled by dis.  agg2 = fp16(dv*(hw2[v]+Σ hw2[s]) + b2).
__global__ void k_gather2(const float* __restrict__ b2) {
    int t = blockIdx.x * blockDim.x + threadIdx.x;
    int v = t >> 3, lane = t & 7;
    if (v >= NN) return;
    int beg = g_rowptr[v], end = g_rowptr[v + 1];
    float dv = g_dis[v];
    const uint4* hw = (const uint4*)g_hw2h;   // 8 uint4 per row

    float a[8], a2[8];
    u4_to_f8(hw[(long long)v * 8 + lane], a);
    #pragma unroll
    for (int i = 0; i < 8; i++) a2[i] = 0.f;

    int p = beg;
    for (; p + 3 < end; p += 4) {
        int s0 = __ldg(&g_esrc[p]);
        int s1 = __ldg(&g_esrc[p + 1]);
        int s2 = __ldg(&g_esrc[p + 2]);
        int s3 = __ldg(&g_esrc[p + 3]);
        uint4 u0 = hw[(long long)s0 * 8 + lane];
        uint4 u1 = hw[(long long)s1 * 8 + lane];
        uint4 u2 = hw[(long long)s2 * 8 + lane];
        uint4 u3 = hw[(long long)s3 * 8 + lane];
        float f0[8], f1[8], f2[8], f3[8];
        u4_to_f8(u0, f0); u4_to_f8(u1, f1); u4_to_f8(u2, f2); u4_to_f8(u3, f3);
        #pragma unroll
        for (int i = 0; i < 8; i++) {
            a[i]  += f0[i]; a2[i] += f1[i];
            a[i]  += f2[i]; a2[i] += f3[i];
        }
    }
    for (; p < end; p++) {
        int s0 = __ldg(&g_esrc[p]);
        float f0[8];
        u4_to_f8(hw[(long long)s0 * 8 + lane], f0);
        #pragma unroll
        for (int i = 0; i < 8; i++) a[i] += f0[i];
    }
    float4 b0 = ((const float4*)b2)[lane * 2];
    float4 b1v = ((const float4*)b2)[lane * 2 + 1];
    float o[8];
    o[0] = fmaf(dv, a[0] + a2[0], b0.x);
    o[1] = fmaf(dv, a[1] + a2[1], b0.y);
    o[2] = fmaf(dv, a[2] + a2[2], b0.z);
    o[3] = fmaf(dv, a[3] + a2[3], b0.w);
    o[4] = fmaf(dv, a[4] + a2[4], b1v.x);
    o[5] = fmaf(dv, a[5] + a2[5], b1v.y);
    o[6] = fmaf(dv, a[6] + a2[6], b1v.z);
    o[7] = fmaf(dv, a[7] + a2[7], b1v.w);
    uint4 u;
    *(__half2*)&u.x = __floats2half2_rn(o[0], o[1]);
    *(__half2*)&u.y = __floats2half2_rn(o[2], o[3]);
    *(__half2*)&u.z = __floats2half2_rn(o[4], o[5]);
    *(__half2*)&u.w = __floats2half2_rn(o[6], o[7]);
    ((uint4*)g_agg2h)[(long long)v * 8 + lane] = u;
}

// ──────────── scoring (8 lanes/edge) + restore g_degi=0 invariant ────────────
__global__ void k_score(const int* __restrict__ pos, const int* __restrict__ neg,
                        int EPn, int SE, int sb, float* __restrict__ out)
{
    if ((int)blockIdx.x >= sb) {   // tail blocks: re-zero degree histogram
        int i = (blockIdx.x - sb) * 256 + threadIdx.x;
        if (i < NN) g_degi[i] = 0;
        return;
    }
    int t = blockIdx.x * blockDim.x + threadIdx.x;
    int e = t >> 3, lane = t & 7;
    if (e >= SE) return;
    int i, j;
    if (e < EPn) { j = pos[e];       i = pos[e + EPn]; }
    else         { j = neg[e - EPn]; i = neg[e];       }
    const uint4* h4 = (const uint4*)g_agg2h;
    float fa[8], fb[8];
    u4_to_f8(h4[(long long)i * 8 + lane], fa);
    u4_to_f8(h4[(long long)j * 8 + lane], fb);
    float s = fa[0] * fb[0] + fa[1] * fb[1] + fa[2] * fb[2] + fa[3] * fb[3]
            + fa[4] * fb[4] + fa[5] * fb[5] + fa[6] * fb[6] + fa[7] * fb[7];
    #pragma unroll
    for (int o = 4; o; o >>= 1) s += __shfl_xor_sync(0xffffffffu, s, o);
    if (lane == 0) out[e] = s;
}

// ───────────────────────── gemm2 wrapper ─────────────────────────
__global__ void __launch_bounds__(256)
k_gemm2(const float* __restrict__ W2)
{
    mma_body<128, 64, 16, 32, 32, 256, true>(blockIdx.x, g_agg1, W2, g_hw2h,
                                             NN, CDIM, HDIM);
}

extern "C" void kernel_launch(void* const* d_in, const int* in_sizes, int n_in,
                              void* d_out, int out_size)
{
    const float* x   = (const float*)d_in[0];
    // d_in[1] = masked_nodes (unused by the reference output)
    const int*   pos = (const int*)d_in[2];
    const int*   neg = (const int*)d_in[3];
    const int*   ei  = (const int*)d_in[4];
    const float* W1  = (const float*)d_in[5];
    const float* b1  = (const float*)d_in[6];
    const float* W2  = (const float*)d_in[7];
    const float* b2  = (const float*)d_in[8];
    float* out = (float*)d_out;

    const int E   = in_sizes[4] / 2;
    const int EPn = in_sizes[2] / 2;
    const int SE  = 2 * EPn;
    const int* src = ei;
    const int* dst = ei + E;

    // gemm1 ∥ degree histogram ∥ output-tail zeroing
    k_mega<<<GB1 + CB + ZB, 256>>>(x, W1, dst, E, out, SE, out_size);

    // fused 3-phase prefix scan (rowptr/cursor/dis)
    k_scan<<<NCSR, 256>>>(E);
    k_bin <<<(E + 255) / 256, 256>>>(src, dst, E);

    k_gather1<<<(NN * 16 + 255) / 256, 256>>>(b1);

    k_gemm2<<<(NN + 127) / 128, 256>>>(W2);
    k_gather2<<<(NN * 8 + 255) / 256, 256>>>(b2);

    const int sb = (SE * 8 + 255) / 256;
    k_score<<<sb + ZD, 256>>>(pos, neg, EPn, SE, sb, out);
}

// round 11
// speedup vs baseline: 1.0856x; 1.0856x over previous
#include <cuda_runtime.h>
#include <cuda_fp16.h>

#define NN   100000
#define FIN  256
#define HDIM 128
#define CDIM 64
#define MAXE 1600000
#define NCSR 148                  // scan-pipeline blocks (co-resident wave 1)
#define GB1  ((NN + 127) / 128)   // gemm1 tiles = 782
#define CB   391                  // histogram blocks in mega
#define ZB   128                  // tail-zero blocks in mega
#define ZD   ((NN + 255) / 256)   // deg-zero blocks appended to score

// Scratch (static device globals — allocation-free per harness rules)
__device__ int     g_degi[NN];              // zeroed at END of each call (k_score)
__device__ int     g_rowptr[NN + 1];
__device__ int     g_bsum[NCSR];
__device__ int     g_boff[NCSR];
__device__ int     g_cursor[NN];
__device__ int     g_esrc[MAXE];            // edge sources grouped by dst (CSR)
__device__ float   g_dis[NN];
__device__ __half2 g_hw1h[NN * HDIM / 2];   // fp16: (x@W1)[v]  (UNSCALED)
__device__ float   g_agg1[NN * HDIM];       // fp32: relu(layer-1 aggregate)
__device__ __half2 g_hw2h[NN * CDIM / 2];   // fp16: dis[v]*(agg1@W2)[v]
__device__ __half2 g_agg2h[NN * CDIM / 2];  // fp16: final h2
__device__ int     g_barc;                  // barrier arrive counter
__device__ int     g_barg;                  // barrier generation

__device__ __forceinline__ void cp_async16(void* smem, const void* gmem) {
    unsigned s = (unsigned)__cvta_generic_to_shared(smem);
    asm volatile("cp.async.ca.shared.global [%0], [%1], 16;\n" :: "r"(s), "l"(gmem));
}
__device__ __forceinline__ void cp_commit() { asm volatile("cp.async.commit_group;\n"); }
__device__ __forceinline__ void cp_wait0()  { asm volatile("cp.async.wait_group 0;\n" ::: "memory"); }

__device__ __forceinline__ unsigned f2tf32(float f) {
    unsigned u;
    asm("cvt.rna.tf32.f32 %0, %1;\n" : "=r"(u) : "f"(f));
    return u;
}

__device__ __forceinline__ void mma_tf32(float* d, const unsigned* a, const unsigned* b) {
    asm volatile(
        "mma.sync.aligned.m16n8k8.row.col.f32.tf32.tf32.f32 "
        "{%0,%1,%2,%3}, {%4,%5,%6,%7}, {%8,%9}, {%0,%1,%2,%3};\n"
        : "+f"(d[0]), "+f"(d[1]), "+f"(d[2]), "+f"(d[3])
        : "r"(a[0]), "r"(a[1]), "r"(a[2]), "r"(a[3]), "r"(b[0]), "r"(b[1]));
}

__device__ __forceinline__ void u4_to_f8(uint4 u, float* f) {
    float2 t;
    t = __half22float2(*(__half2*)&u.x); f[0] = t.x; f[1] = t.y;
    t = __half22float2(*(__half2*)&u.y); f[2] = t.x; f[3] = t.y;
    t = __half22float2(*(__half2*)&u.z); f[4] = t.x; f[5] = t.y;
    t = __half22float2(*(__half2*)&u.w); f[6] = t.x; f[7] = t.y;
}

// Grid barrier among NCSR co-resident blocks.
__device__ __forceinline__ void csr_barrier() {
    __syncthreads();
    if (threadIdx.x == 0) {
        int gen = atomicAdd(&g_barg, 0);
        __threadfence();
        int t = atomicAdd(&g_barc, 1);
        if (t == NCSR - 1) {
            atomicExch(&g_barc, 0);
            __threadfence();
            atomicAdd(&g_barg, 1);
        } else {
            while (atomicAdd(&g_barg, 0) == gen) { __nanosleep(64); }
        }
    }
    __syncthreads();
}

// ───────────────────────── TF32 tensor-core GEMM body ─────────────────────────
// SCALE_DIS ? C = fp16(dis[row]*(A@B)) : C = fp16(A@B).
// NOTE: g_* pointers must be resolved in DEVICE code (host shadow-symbol trap).
template<int BM, int BN, int BK, int WM, int WN, int NT, bool SCALE_DIS>
__device__ __forceinline__ void mma_body(
    int bx, const float* __restrict__ A, const float* __restrict__ Bg,
    __half2* __restrict__ C, int M, int N, int K)
{
    constexpr int BKp = BK + 4;
    constexpr int BNp = BN + 8;
    __shared__ float As[2][BM][BKp];
    __shared__ float Bs[2][BK][BNp];

    const int tid  = threadIdx.x;
    const int wid  = tid >> 5;
    const int lane = tid & 31;
    const int grp  = lane >> 2;
    const int qi   = lane & 3;
    constexpr int NWN = BN / WN;
    const int warp_m = wid / NWN;
    const int warp_n = wid % NWN;
    constexpr int MF = WM / 16;
    constexpr int NF = WN / 8;

    const int brow = bx * BM;

    float acc[MF][NF][4];
    #pragma unroll
    for (int i = 0; i < MF; i++)
        #pragma unroll
        for (int j = 0; j < NF; j++)
            #pragma unroll
            for (int q = 0; q < 4; q++) acc[i][j][q] = 0.0f;

    constexpr int AIT = (BM * BK / 4) / NT;
    constexpr int BIT = (BK * BN / 4) / NT;

    auto cpA = [&](int buf, int k0) {
        #pragma unroll
        for (int it = 0; it < AIT; it++) {
            int idx  = tid + it * NT;
            int row  = idx / (BK / 4);
            int kc   = (idx % (BK / 4)) * 4;
            int grow = brow + row;
            if (grow > M - 1) grow = M - 1;
            cp_async16(&As[buf][row][kc], A + (long long)grow * K + k0 + kc);
        }
    };
    auto cpB = [&](int buf, int k0) {
        #pragma unroll
        for (int it = 0; it < BIT; it++) {
            int idx = tid + it * NT;
            int kk  = idx / (BN / 4);
            int nc  = (idx % (BN / 4)) * 4;
            cp_async16(&Bs[buf][kk][nc], Bg + (long long)(k0 + kk) * N + nc);
        }
    };
    auto compute = [&](int buf) {
        #pragma unroll
        for (int ks = 0; ks < BK / 8; ks++) {
            int kk = ks * 8;
            unsigned a[MF][4], b[NF][2];
            #pragma unroll
            for (int fm = 0; fm < MF; fm++) {
                const float* ap = &As[buf][warp_m * WM + fm * 16 + grp][kk + qi];
                a[fm][0] = f2tf32(ap[0]);
                a[fm][1] = f2tf32(ap[8 * BKp]);
                a[fm][2] = f2tf32(ap[4]);
                a[fm][3] = f2tf32(ap[8 * BKp + 4]);
            }
            #pragma unroll
            for (int fn = 0; fn < NF; fn++) {
                const float* bp = &Bs[buf][kk + qi][warp_n * WN + fn * 8 + grp];
                b[fn][0] = f2tf32(bp[0]);
                b[fn][1] = f2tf32(bp[4 * BNp]);
            }
            #pragma unroll
            for (int fm = 0; fm < MF; fm++)
                #pragma unroll
                for (int fn = 0; fn < NF; fn++)
                    mma_tf32(acc[fm][fn], a[fm], b[fn]);
        }
    };

    cpA(0, 0); cpB(0, 0); cp_commit();
    cp_wait0(); __syncthreads();

    const int KT = K / BK;
    for (int t = 1; t < KT; t++) {
        cpA(t & 1, t * BK); cpB(t & 1, t * BK); cp_commit();
        compute((t - 1) & 1);
        cp_wait0(); __syncthreads();
    }
    compute((KT - 1) & 1);

    #pragma unroll
    for (int fm = 0; fm < MF; fm++) {
        int r0 = brow + warp_m * WM + fm * 16 + grp;
        int r1 = r0 + 8;
        float d0 = 1.0f, d1 = 1.0f;
        if (SCALE_DIS) {
            d0 = (r0 < M) ? g_dis[r0] : 0.0f;
            d1 = (r1 < M) ? g_dis[r1] : 0.0f;
        }
        #pragma unroll
        for (int fn = 0; fn < NF; fn++) {
            int col = warp_n * WN + fn * 8 + 2 * qi;
            if (r0 < M)
                C[((long long)r0 * N + col) >> 1] =
                    __floats2half2_rn(acc[fm][fn][0] * d0, acc[fm][fn][1] * d0);
            if (r1 < M)
                C[((long long)r1 * N + col) >> 1] =
                    __floats2half2_rn(acc[fm][fn][2] * d1, acc[fm][fn][3] * d1);
        }
    }
}

// ───────────────────────── mega: gemm1 ∥ histogram ∥ tail-zero ─────────────────
// g_degi enters this kernel ZEROED (invariant maintained by k_score's tail).
__global__ void __launch_bounds__(256)
k_mega(const float* __restrict__ x, const float* __restrict__ W1,
       const int* __restrict__ dst, int E,
       float* __restrict__ out, int SE, int total)
{
    int bx = blockIdx.x;
    if (bx < GB1) {   // gemm1: hw1h = fp16(x @ W1), unscaled
        mma_body<128, 128, 16, 64, 32, 256, false>(bx, x, W1, g_hw1h, NN, HDIM, FIN);
        return;
    }
    bx -= GB1;
    if (bx < CB) {    // degree histogram
        for (int e = bx * 256 + threadIdx.x; e < E; e += CB * 256)
            atomicAdd(&g_degi[dst[e]], 1);
        return;
    }
    bx -= CB;         // zero the tail of the output
    for (int i = SE + bx * 256 + threadIdx.x; i < total; i += ZB * 256)
        out[i] = 0.0f;
}

// ───────────────────────── fused 3-phase scan (148 blocks, grid barriers) ──────
__global__ void __launch_bounds__(256)
k_scan(int E)
{
    const int c   = blockIdx.x;
    const int tid = threadIdx.x;
    __shared__ int sc[256];
    const int chunk = (NN + NCSR - 1) / NCSR;
    const int lo = c * chunk;
    const int hi = (lo + chunk < NN) ? lo + chunk : NN;

    // Phase A: per-block chunk sums.
    {
        int s = 0;
        for (int i = lo + tid; i < hi; i += 256) s += g_degi[i];
        sc[tid] = s; __syncthreads();
        #pragma unroll
        for (int o = 128; o; o >>= 1) {
            if (tid < o) sc[tid] += sc[tid + o];
            __syncthreads();
        }
        if (tid == 0) g_bsum[c] = sc[0];
    }
    csr_barrier();

    // Phase B: block 0 exclusive-scans the chunk sums.
    if (c == 0) {
        int v = (tid < NCSR) ? g_bsum[tid] : 0;
        sc[tid] = v; __syncthreads();
        #pragma unroll
        for (int o = 1; o < 256; o <<= 1) {
            int t2 = (tid >= o) ? sc[tid - o] : 0;
            __syncthreads();
            sc[tid] += t2;
            __syncthreads();
        }
        if (tid < NCSR) g_boff[tid] = sc[tid] - v;
    }
    csr_barrier();

    // Phase C: rowptr / cursor / dis over the chunk.
    {
        int running = g_boff[c];
        for (int base = lo; base < hi; base += 256) {
            int i = base + tid;
            int d = (i < hi) ? g_degi[i] : 0;
            sc[tid] = d; __syncthreads();
            #pragma unroll
            for (int o = 1; o < 256; o <<= 1) {
                int t2 = (tid >= o) ? sc[tid - o] : 0;
                __syncthreads();
                sc[tid] += t2;
                __syncthreads();
            }
            if (i < hi) {
                int r = running + sc[tid] - d;
                g_rowptr[i] = r;
                g_cursor[i] = r;
                g_dis[i]    = rsqrtf((float)d + 1.0f);
            }
            running += sc[255];
            __syncthreads();
        }
        if (c == 0 && tid == 0) g_rowptr[NN] = E;
    }
}

__global__ void k_bin(const int* __restrict__ src, const int* __restrict__ dst, int E) {
    int e = blockIdx.x * blockDim.x + threadIdx.x;
    if (e >= E) return;
    int d = dst[e];
    int p = atomicAdd(&g_cursor[d], 1);
    g_esrc[p] = src[e];
}

// ───────────── gather aggregation: 2 uint4 per lane (high MLP) ─────────────
// Layer 1: hw1h UNSCALED.  S = dv*h1[v] + Σ_e ds*h1[s];  agg1 = relu(dv*S + b1).
// 8 lanes per node; lane covers uint4 indices {lane, lane+8} of the 16-uint4 row.
__global__ void k_gather1(const float* __restrict__ b1) {
    int t = blockIdx.x * blockDim.x + threadIdx.x;
    int v = t >> 3, lane = t & 7;
    if (v >= NN) return;
    int beg = g_rowptr[v], end = g_rowptr[v + 1];
    float dv = g_dis[v];
    const uint4* hw = (const uint4*)g_hw1h;   // 16 uint4 per row

    float a[16];
    {
        uint4 u0 = hw[(long long)v * 16 + lane];
        uint4 u1 = hw[(long long)v * 16 + lane + 8];
        float f0[8], f1[8];
        u4_to_f8(u0, f0); u4_to_f8(u1, f1);
        #pragma unroll
        for (int i = 0; i < 8; i++) { a[i] = dv * f0[i]; a[8 + i] = dv * f1[i]; }
    }

    int p = beg;
    for (; p + 1 < end; p += 2) {
        int s0 = __ldg(&g_esrc[p]);
        int s1 = __ldg(&g_esrc[p + 1]);
        float d0 = g_dis[s0], d1 = g_dis[s1];
        uint4 u00 = hw[(long long)s0 * 16 + lane];
        uint4 u01 = hw[(long long)s0 * 16 + lane + 8];
        uint4 u10 = hw[(long long)s1 * 16 + lane];
        uint4 u11 = hw[(long long)s1 * 16 + lane + 8];
        float f00[8], f01[8], f10[8], f11[8];
        u4_to_f8(u00, f00); u4_to_f8(u01, f01);
        u4_to_f8(u10, f10); u4_to_f8(u11, f11);
        #pragma unroll
        for (int i = 0; i < 8; i++) {
            a[i]     = fmaf(d0, f00[i], a[i]);
            a[8 + i] = fmaf(d0, f01[i], a[8 + i]);
            a[i]     = fmaf(d1, f10[i], a[i]);
            a[8 + i] = fmaf(d1, f11[i], a[8 + i]);
        }
    }
    if (p < end) {
        int s0 = __ldg(&g_esrc[p]);
        float d0 = g_dis[s0];
        uint4 u00 = hw[(long long)s0 * 16 + lane];
        uint4 u01 = hw[(long long)s0 * 16 + lane + 8];
        float f00[8], f01[8];
        u4_to_f8(u00, f00); u4_to_f8(u01, f01);
        #pragma unroll
        for (int i = 0; i < 8; i++) {
            a[i]     = fmaf(d0, f00[i], a[i]);
            a[8 + i] = fmaf(d0, f01[i], a[8 + i]);
        }
    }

    const float4* bb = (const float4*)b1;
    float o[16];
    #pragma unroll
    for (int h = 0; h < 2; h++) {
        float4 c0 = bb[h * 16 + lane * 2];
        float4 c1 = bb[h * 16 + lane * 2 + 1];
        o[h*8+0] = fmaxf(fmaf(dv, a[h*8+0], c0.x), 0.f);
        o[h*8+1] = fmaxf(fmaf(dv, a[h*8+1], c0.y), 0.f);
        o[h*8+2] = fmaxf(fmaf(dv, a[h*8+2], c0.z), 0.f);
        o[h*8+3] = fmaxf(fmaf(dv, a[h*8+3], c0.w), 0.f);
        o[h*8+4] = fmaxf(fmaf(dv, a[h*8+4], c1.x), 0.f);
        o[h*8+5] = fmaxf(fmaf(dv, a[h*8+5], c1.y), 0.f);
        o[h*8+6] = fmaxf(fmaf(dv, a[h*8+6], c1.z), 0.f);
        o[h*8+7] = fmaxf(fmaf(dv, a[h*8+7], c1.w), 0.f);
        float4* outp = (float4*)(g_agg1 + (long long)v * HDIM + h * 64 + lane * 8);
        outp[0] = make_float4(o[h*8+0], o[h*8+1], o[h*8+2], o[h*8+3]);
        outp[1] = make_float4(o[h*8+4], o[h*8+5], o[h*8+6], o[h*8+7]);
    }
}

// Layer 2: hw2h pre-scaled by dis.  agg2 = fp16(dv*(hw2[v]+Σ hw2[s]) + b2).
// 4 lanes per node; lane covers uint4 indices {lane, lane+4} of the 8-uint4 row.
__global__ void k_gather2(const float* __restrict__ b2) {
    int t = blockIdx.x * blockDim.x + threadIdx.x;
    int v = t >> 2, lane = t & 3;
    if (v >= NN) return;
    int beg = g_rowptr[v], end = g_rowptr[v + 1];
    float dv = g_dis[v];
    const uint4* hw = (const uint4*)g_hw2h;   // 8 uint4 per row

    float a[16];
    {
        uint4 u0 = hw[(long long)v * 8 + lane];
        uint4 u1 = hw[(long long)v * 8 + lane + 4];
        float f0[8], f1[8];
        u4_to_f8(u0, f0); u4_to_f8(u1, f1);
        #pragma unroll
        for (int i = 0; i < 8; i++) { a[i] = f0[i]; a[8 + i] = f1[i]; }
    }

    int p = beg;
    for (; p + 1 < end; p += 2) {
        int s0 = __ldg(&g_esrc[p]);
        int s1 = __ldg(&g_esrc[p + 1]);
        uint4 u00 = hw[(long long)s0 * 8 + lane];
        uint4 u01 = hw[(long long)s0 * 8 + lane + 4];
        uint4 u10 = hw[(long long)s1 * 8 + lane];
        uint4 u11 = hw[(long long)s1 * 8 + lane + 4];
        float f00[8], f01[8], f10[8], f11[8];
        u4_to_f8(u00, f00); u4_to_f8(u01, f01);
        u4_to_f8(u10, f10); u4_to_f8(u11, f11);
        #pragma unroll
        for (int i = 0; i < 8; i++) {
            a[i]     += f00[i] + f10[i];
            a[8 + i] += f01[i] + f11[i];
        }
    }
    if (p < end) {
        int s0 = __ldg(&g_esrc[p]);
        uint4 u00 = hw[(long long)s0 * 8 + lane];
        uint4 u01 = hw[(long long)s0 * 8 + lane + 4];
        float f00[8], f01[8];
        u4_to_f8(u00, f00); u4_to_f8(u01, f01);
        #pragma unroll
        for (int i = 0; i < 8; i++) { a[i] += f00[i]; a[8 + i] += f01[i]; }
    }

    const float4* bb = (const float4*)b2;
    #pragma unroll
    for (int h = 0; h < 2; h++) {
        float4 c0 = bb[h * 8 + lane * 2];
        float4 c1 = bb[h * 8 + lane * 2 + 1];
        float o0 = fmaf(dv, a[h*8+0], c0.x);
        float o1 = fmaf(dv, a[h*8+1], c0.y);
        float o2 = fmaf(dv, a[h*8+2], c0.z);
        float o3 = fmaf(dv, a[h*8+3], c0.w);
        float o4 = fmaf(dv, a[h*8+4], c1.x);
        float o5 = fmaf(dv, a[h*8+5], c1.y);
        float o6 = fmaf(dv, a[h*8+6], c1.z);
        float o7 = fmaf(dv, a[h*8+7], c1.w);
        uint4 u;
        *(__half2*)&u.x = __floats2half2_rn(o0, o1);
        *(__half2*)&u.y = __floats2half2_rn(o2, o3);
        *(__half2*)&u.z = __floats2half2_rn(o4, o5);
        *(__half2*)&u.w = __floats2half2_rn(o6, o7);
        ((uint4*)g_agg2h)[(long long)v * 8 + h * 4 + lane] = u;
    }
}

// ──────── scoring (4 lanes/edge, 2 uint4 per side) + restore g_degi=0 ────────
__global__ void k_score(const int* __restrict__ pos, const int* __restrict__ neg,
                        int EPn, int SE, int sb, float* __restrict__ out)
{
    if ((int)blockIdx.x >= sb) {   // tail blocks: re-zero degree histogram
        int i = (blockIdx.x - sb) * 256 + threadIdx.x;
        if (i < NN) g_degi[i] = 0;
        return;
    }
    int t = blockIdx.x * blockDim.x + threadIdx.x;
    int e = t >> 2, lane = t & 3;
    if (e >= SE) return;
    int i, j;
    if (e < EPn) { j = pos[e];       i = pos[e + EPn]; }
    else         { j = neg[e - EPn]; i = neg[e];       }
    const uint4* h4 = (const uint4*)g_agg2h;
    uint4 ua0 = h4[(long long)i * 8 + lane];
    uint4 ua1 = h4[(long long)i * 8 + lane + 4];
    uint4 ub0 = h4[(long long)j * 8 + lane];
    uint4 ub1 = h4[(long long)j * 8 + lane + 4];
    float fa0[8], fa1[8], fb0[8], fb1[8];
    u4_to_f8(ua0, fa0); u4_to_f8(ua1, fa1);
    u4_to_f8(ub0, fb0); u4_to_f8(ub1, fb1);
    float s = 0.f;
    #pragma unroll
    for (int q = 0; q < 8; q++) s = fmaf(fa0[q], fb0[q], s);
    #pragma unroll
    for (int q = 0; q < 8; q++) s = fmaf(fa1[q], fb1[q], s);
    s += __shfl_xor_sync(0xffffffffu, s, 2);
    s += __shfl_xor_sync(0xffffffffu, s, 1);
    if (lane == 0) out[e] = s;
}

// ───────────────────────── gemm2 wrapper ─────────────────────────
__global__ void __launch_bounds__(256)
k_gemm2(const float* __restrict__ W2)
{
    mma_body<128, 64, 16, 32, 32, 256, true>(blockIdx.x, g_agg1, W2, g_hw2h,
                                             NN, CDIM, HDIM);
}

extern "C" void kernel_launch(void* const* d_in, const int* in_sizes, int n_in,
                              void* d_out, int out_size)
{
    const float* x   = (const float*)d_in[0];
    // d_in[1] = masked_nodes (unused by the reference output)
    const int*   pos = (const int*)d_in[2];
    const int*   neg = (const int*)d_in[3];
    const int*   ei  = (const int*)d_in[4];
    const float* W1  = (const float*)d_in[5];
    const float* b1  = (const float*)d_in[6];
    const float* W2  = (const float*)d_in[7];
    const float* b2  = (const float*)d_in[8];
    float* out = (float*)d_out;

    const int E   = in_sizes[4] / 2;
    const int EPn = in_sizes[2] / 2;
    const int SE  = 2 * EPn;
    const int* src = ei;
    const int* dst = ei + E;

    // gemm1 ∥ degree histogram ∥ output-tail zeroing
    k_mega<<<GB1 + CB + ZB, 256>>>(x, W1, dst, E, out, SE, out_size);

    // fused 3-phase prefix scan (rowptr/cursor/dis)
    k_scan<<<NCSR, 256>>>(E);
    k_bin <<<(E + 255) / 256, 256>>>(src, dst, E);

    k_gather1<<<(NN * 8 + 255) / 256, 256>>>(b1);

    k_gemm2<<<(NN + 127) / 128, 256>>>(W2);
    k_gather2<<<(NN * 4 + 255) / 256, 256>>>(b2);

    const int sb = (SE * 4 + 255) / 256;
    k_score<<<sb + ZD, 256>>>(pos, neg, EPn, SE, sb, out);
}